// round 2
// baseline (speedup 1.0000x reference)
#include <cuda_runtime.h>
#include <math_constants.h>

// Static device scratch (no allocation allowed anywhere).
#define MAX_SEGS 8192
__device__ int g_seg_start[MAX_SEGS + 1];
__device__ int g_is64;   // 1 if batch buffer is int64 (little-endian), else int32

// ---------------------------------------------------------------------------
// Kernel 0a: init seg_start to n (so unwritten entries -> empty segments,
// never garbage indices).
// ---------------------------------------------------------------------------
__global__ void seg_init_kernel(int n, int G) {
    int g = blockIdx.x * blockDim.x + threadIdx.x;
    if (g <= G) g_seg_start[g] = n;
}

// ---------------------------------------------------------------------------
// Kernel 0b: dtype probe. If the buffer holds int64 values in [0, G), the
// odd 32-bit words (high halves) of the first min(4096, n) words are all 0.
// For int32 sorted data, odd words hold real segment ids (>0 long before
// word 4096 since N/G ~ 390). Reads stay within 4*n bytes (valid either way).
// ---------------------------------------------------------------------------
__global__ void dtype_probe_kernel(const int* __restrict__ b32, int n) {
    __shared__ long long red[256];
    int limit = n < 4096 ? n : 4096;
    long long acc = 0;
    for (int i = 2 * threadIdx.x + 1; i < limit; i += 512)
        acc += (long long)b32[i];
    red[threadIdx.x] = acc;
    __syncthreads();
    for (int off = 128; off > 0; off >>= 1) {
        if (threadIdx.x < off) red[threadIdx.x] += red[threadIdx.x + off];
        __syncthreads();
    }
    if (threadIdx.x == 0) g_is64 = (red[0] == 0) ? 1 : 0;
}

// ---------------------------------------------------------------------------
// Kernel 1: boundary detection on the sorted batch array.
// Thread i compares batch[i] vs batch[i-1]; writes seg_start for every
// segment id in (batch[i-1], batch[i]] (covers empty segments too).
// ---------------------------------------------------------------------------
__global__ void seg_bounds_kernel(const void* __restrict__ batch, int n, int G) {
    int i = blockIdx.x * blockDim.x + threadIdx.x;
    if (i >= n) return;
    int cur, prev;
    if (g_is64) {
        const long long* b = (const long long*)batch;
        cur  = (int)b[i];
        prev = (i == 0) ? -1 : (int)b[i - 1];
    } else {
        const int* b = (const int*)batch;
        cur  = b[i];
        prev = (i == 0) ? -1 : b[i - 1];
    }
    if (cur > G) cur = G;
    if (prev < -1) prev = -1;
    for (int g = prev + 1; g <= cur && g <= G; ++g) g_seg_start[g] = i;
    // Tail segments (> last id) keep their init value n.
}

// ---------------------------------------------------------------------------
// Online logsumexp update with a SINGLE exp per element:
//   d = x - m;  e = exp(-|d|)
//   d > 0 : s = s*e + 1 ; m = x      (e = exp(m_old - x))
//   else  : s = s + e                (e = exp(x - m))
// Both arms are selects -> fully predicated, no divergence.
// ---------------------------------------------------------------------------
__device__ __forceinline__ void lse_update(float x, float& m, float& s) {
    float d  = x - m;
    float e  = __expf(-fabsf(d));
    bool  gt = d > 0.0f;
    s = gt ? fmaf(s, e, 1.0f) : (s + e);
    m = gt ? x : m;
}

__device__ __forceinline__ void upd4(float4 v, float m[4], float s[4]) {
    lse_update(v.x, m[0], s[0]);
    lse_update(v.y, m[1], s[1]);
    lse_update(v.z, m[2], s[2]);
    lse_update(v.w, m[3], s[3]);
}

// ---------------------------------------------------------------------------
// Kernel 2: one block per (segment, 128-column half).
// 256 threads = 32 float4-lanes (128 cols) x 8 row-groups. Each thread keeps
// 4 independent (m, s) accumulators; streams rows with stride 8, 4-deep
// unroll for MLP. Final 8-way merge via smem.
// ---------------------------------------------------------------------------
__global__ __launch_bounds__(256, 4)
void pool_lse_kernel(const float* __restrict__ feats, float* __restrict__ out,
                     int D, int n) {
    const int g      = blockIdx.x;
    const int colblk = blockIdx.y * 128;
    const int lane   = threadIdx.x & 31;
    const int rg     = threadIdx.x >> 5;
    const int c4     = (colblk >> 2) + lane;

    int start = g_seg_start[g];
    int end   = g_seg_start[g + 1];
    if (start < 0) start = 0;
    if (end > n)   end = n;

    float m[4], s[4];
#pragma unroll
    for (int j = 0; j < 4; ++j) { m[j] = -CUDART_INF_F; s[j] = 0.0f; }

    const float4* __restrict__ f4 = (const float4*)feats;
    const int d4 = D >> 2;

    int r = start + rg;
    for (; r + 24 < end; r += 32) {
        float4 v0 = __ldg(&f4[(size_t)(r     ) * d4 + c4]);
        float4 v1 = __ldg(&f4[(size_t)(r +  8) * d4 + c4]);
        float4 v2 = __ldg(&f4[(size_t)(r + 16) * d4 + c4]);
        float4 v3 = __ldg(&f4[(size_t)(r + 24) * d4 + c4]);
        upd4(v0, m, s);
        upd4(v1, m, s);
        upd4(v2, m, s);
        upd4(v3, m, s);
    }
    for (; r < end; r += 8) {
        float4 v = __ldg(&f4[(size_t)r * d4 + c4]);
        upd4(v, m, s);
    }

    __shared__ float sm_m[8][128];
    __shared__ float sm_s[8][128];
#pragma unroll
    for (int j = 0; j < 4; ++j) {
        sm_m[rg][lane * 4 + j] = m[j];
        sm_s[rg][lane * 4 + j] = s[j];
    }
    __syncthreads();

    if (threadIdx.x < 128) {
        const int c = threadIdx.x;
        float out_val;
        if (start >= end) {
            out_val = -27.631021115928547f;   // log(1e-12): empty segment
        } else {
            float M = sm_m[0][c];
#pragma unroll
            for (int k = 1; k < 8; ++k) M = fmaxf(M, sm_m[k][c]);
            float S = 0.0f;
#pragma unroll
            for (int k = 0; k < 8; ++k) {
                // Empty row-group: m=-inf, s=0 -> exp(-inf)=0 -> adds 0.
                S += sm_s[k][c] * __expf(sm_m[k][c] - M);
            }
            out_val = __logf(S) + M;          // S >= 1 here, clamp unnecessary
        }
        out[(size_t)g * D + colblk + c] = out_val;
    }
}

// ---------------------------------------------------------------------------
// Inputs (metadata order): feats f32 [N*D], batch int [N], num_segments.
// ---------------------------------------------------------------------------
extern "C" void kernel_launch(void* const* d_in, const int* in_sizes, int n_in,
                              void* d_out, int out_size) {
    const float* feats = (const float*)d_in[0];
    const void*  batch = d_in[1];

    const int n = in_sizes[1];                // rows (200000)
    const int D = in_sizes[0] / n;            // features (256)
    const int G = out_size / D;               // segments (512)

    seg_init_kernel<<<(G + 256) / 256, 256>>>(n, G);
    dtype_probe_kernel<<<1, 256>>>((const int*)batch, n);
    seg_bounds_kernel<<<(n + 255) / 256, 256>>>(batch, n, G);

    dim3 grid(G, D / 128);
    pool_lse_kernel<<<grid, 256>>>(feats, (float*)d_out, D, n);
}